// round 1
// baseline (speedup 1.0000x reference)
#include <cuda_runtime.h>
#include <math.h>

#define BB 8
#define NN 1024
#define DD 256
#define HH 8
#define HD 32
#define ROWS (BB*NN)          // 8192
#define ELEMS (ROWS*DD)       // 2097152

// -------- scratch (static device globals; no allocation) --------
__device__ float g_q[ELEMS];
__device__ float g_k[ELEMS];
__device__ float g_v[ELEMS];
__device__ float g_o[ELEMS];
__device__ float g_t[ELEMS];
__device__ float g_u[ELEMS];

// ---------------- GEMM: C[8192,256] = X[8192,256] @ W[256,256] + bias ----------------
// MODE 0: projection, zero rows with n >= lengths[b]
// MODE 1: C = X + relu(X@W + bias)   (residual MLP)
template<int MODE>
__global__ void __launch_bounds__(256) gemm_kernel(
    const float* __restrict__ X, const float* __restrict__ W,
    const float* __restrict__ bias, float* __restrict__ C,
    const int* __restrict__ lengths)
{
    __shared__ float As[16][68];   // [k][row], padded
    __shared__ float Bs[16][64];   // [k][col]

    const int tid  = threadIdx.x;
    const int brow = blockIdx.x * 64;
    const int bcol = blockIdx.y * 64;
    const int tx = tid & 15;
    const int ty = tid >> 4;

    float acc[4][4];
    #pragma unroll
    for (int i = 0; i < 4; i++)
        #pragma unroll
        for (int j = 0; j < 4; j++) acc[i][j] = 0.f;

    for (int k0 = 0; k0 < DD; k0 += 16) {
        {   // load A tile (64 rows x 16 k), one float4 per thread
            int r  = tid >> 2;
            int kc = (tid & 3) << 2;
            float4 xv = *(const float4*)&X[(size_t)(brow + r) * DD + k0 + kc];
            As[kc+0][r] = xv.x; As[kc+1][r] = xv.y;
            As[kc+2][r] = xv.z; As[kc+3][r] = xv.w;
        }
        {   // load B tile (16 k x 64 cols), one float4 per thread
            int r = tid >> 4;
            int c = (tid & 15) << 2;
            *(float4*)&Bs[r][c] = *(const float4*)&W[(size_t)(k0 + r) * DD + bcol + c];
        }
        __syncthreads();

        #pragma unroll
        for (int kk = 0; kk < 16; kk++) {
            float4 a4 = *(const float4*)&As[kk][ty << 2];
            float4 b4 = *(const float4*)&Bs[kk][tx << 2];
            float a[4] = {a4.x, a4.y, a4.z, a4.w};
            float b[4] = {b4.x, b4.y, b4.z, b4.w};
            #pragma unroll
            for (int i = 0; i < 4; i++)
                #pragma unroll
                for (int j = 0; j < 4; j++)
                    acc[i][j] += a[i] * b[j];
        }
        __syncthreads();
    }

    #pragma unroll
    for (int i = 0; i < 4; i++) {
        int gr = brow + (ty << 2) + i;
        int bidx = gr >> 10;
        int nidx = gr & 1023;
        #pragma unroll
        for (int j = 0; j < 4; j++) {
            int gc = bcol + (tx << 2) + j;
            float c = acc[i][j] + bias[gc];
            if (MODE == 0) {
                if (nidx >= lengths[bidx]) c = 0.f;
            } else {
                float t = X[(size_t)gr * DD + gc];
                c = t + fmaxf(c, 0.f);
            }
            C[(size_t)gr * DD + gc] = c;
        }
    }
}

// ---------------- Attention: per (b,h), O = qh + softmax_raw(q k^T/16) @ vh ----------------
// 128 threads = 128 query rows per block; grid (N/128, H, B)
__global__ void __launch_bounds__(128) attn_kernel(
    const float* __restrict__ q, const float* __restrict__ k,
    const float* __restrict__ v, const int* __restrict__ lengths,
    float* __restrict__ o)
{
    const int b = blockIdx.z;
    const int h = blockIdx.y;
    const int n = blockIdx.x * 128 + threadIdx.x;
    const int len = lengths[b];

    __shared__ float ks[64][32];
    __shared__ float vs[64][32];

    const float* qrow = q + ((size_t)b * NN + n) * DD + h * HD;
    float qr[HD];
    #pragma unroll
    for (int j = 0; j < HD; j += 4) {
        float4 t = *(const float4*)&qrow[j];
        qr[j] = t.x; qr[j+1] = t.y; qr[j+2] = t.z; qr[j+3] = t.w;
    }

    float acc[HD];
    #pragma unroll
    for (int j = 0; j < HD; j++) acc[j] = 0.f;
    float esum = 0.f;
    const bool active = (n < len);

    const float* kbase = k + (size_t)b * NN * DD + h * HD;
    const float* vbase = v + (size_t)b * NN * DD + h * HD;

    for (int m0 = 0; m0 < len; m0 += 64) {
        __syncthreads();   // protect previous tile reads
        #pragma unroll
        for (int i = 0; i < 4; i++) {
            int idx = threadIdx.x + i * 128;   // 0..511 float4 slots
            int r = idx >> 3;
            int c = (idx & 7) << 2;
            size_t off = (size_t)(m0 + r) * DD + c;
            *(float4*)&ks[r][c] = *(const float4*)&kbase[off];
            *(float4*)&vs[r][c] = *(const float4*)&vbase[off];
        }
        __syncthreads();

        const int mEnd = min(64, len - m0);
        if (active) {
            for (int mm = 0; mm < mEnd; mm++) {
                const float4* k4 = (const float4*)ks[mm];
                float s = 0.f;
                #pragma unroll
                for (int j4 = 0; j4 < 8; j4++) {
                    float4 t = k4[j4];
                    s += qr[j4*4+0]*t.x + qr[j4*4+1]*t.y
                       + qr[j4*4+2]*t.z + qr[j4*4+3]*t.w;
                }
                float e = __expf(s * 0.0625f);   // scale 1/sqrt(DV)=1/16
                esum += e;
                const float4* v4 = (const float4*)vs[mm];
                #pragma unroll
                for (int j4 = 0; j4 < 8; j4++) {
                    float4 t = v4[j4];
                    acc[j4*4+0] += e * t.x;
                    acc[j4*4+1] += e * t.y;
                    acc[j4*4+2] += e * t.z;
                    acc[j4*4+3] += e * t.w;
                }
            }
        }
    }

    float inv = active ? (1.f / (esum + 1e-15f)) : 0.f;
    float* orow = o + ((size_t)b * NN + n) * DD + h * HD;
    #pragma unroll
    for (int j = 0; j < HD; j += 4) {
        float4 t;
        t.x = active ? (qr[j+0] + acc[j+0] * inv) : 0.f;
        t.y = active ? (qr[j+1] + acc[j+1] * inv) : 0.f;
        t.z = active ? (qr[j+2] + acc[j+2] * inv) : 0.f;
        t.w = active ? (qr[j+3] + acc[j+3] * inv) : 0.f;
        *(float4*)&orow[j] = t;
    }
}

// ---------------- LayerNorm over last dim (256), one block per row ----------------
__global__ void __launch_bounds__(256) ln_kernel(
    const float* __restrict__ x, const float* __restrict__ g,
    const float* __restrict__ b, float* __restrict__ y)
{
    const int row = blockIdx.x;
    const int t = threadIdx.x;
    __shared__ float sred[8];

    float v = x[(size_t)row * DD + t];

    float s = v;
    #pragma unroll
    for (int o = 16; o > 0; o >>= 1) s += __shfl_xor_sync(0xFFFFFFFFu, s, o);
    if ((t & 31) == 0) sred[t >> 5] = s;
    __syncthreads();
    float mu = 0.f;
    #pragma unroll
    for (int i = 0; i < 8; i++) mu += sred[i];
    mu *= (1.f / 256.f);

    float d = v - mu;
    float sq = d * d;
    #pragma unroll
    for (int o = 16; o > 0; o >>= 1) sq += __shfl_xor_sync(0xFFFFFFFFu, sq, o);
    __syncthreads();   // everyone done reading sred
    if ((t & 31) == 0) sred[t >> 5] = sq;
    __syncthreads();
    float var = 0.f;
    #pragma unroll
    for (int i = 0; i < 8; i++) var += sred[i];
    var *= (1.f / 256.f);

    float r = rsqrtf(var + 1e-5f);
    y[(size_t)row * DD + t] = d * r * g[t] + b[t];
}

// ---------------- launch ----------------
extern "C" void kernel_launch(void* const* d_in, const int* in_sizes, int n_in,
                              void* d_out, int out_size)
{
    const float* Q       = (const float*)d_in[0];
    const float* K       = (const float*)d_in[1];
    const int*   lengths = (const int*)  d_in[2];
    const float* Wq      = (const float*)d_in[3];
    const float* bq      = (const float*)d_in[4];
    const float* Wk      = (const float*)d_in[5];
    const float* bk      = (const float*)d_in[6];
    const float* Wv      = (const float*)d_in[7];
    const float* bv      = (const float*)d_in[8];
    const float* Wo      = (const float*)d_in[9];
    const float* bo      = (const float*)d_in[10];
    const float* g0      = (const float*)d_in[11];
    const float* b0      = (const float*)d_in[12];
    const float* g1      = (const float*)d_in[13];
    const float* b1      = (const float*)d_in[14];

    float *sq, *sk, *sv, *so, *st, *su;
    cudaGetSymbolAddress((void**)&sq, g_q);
    cudaGetSymbolAddress((void**)&sk, g_k);
    cudaGetSymbolAddress((void**)&sv, g_v);
    cudaGetSymbolAddress((void**)&so, g_o);
    cudaGetSymbolAddress((void**)&st, g_t);
    cudaGetSymbolAddress((void**)&su, g_u);

    dim3 gg(ROWS / 64, DD / 64);

    gemm_kernel<0><<<gg, 256>>>(Q, Wq, bq, sq, lengths);
    gemm_kernel<0><<<gg, 256>>>(K, Wk, bk, sk, lengths);
    gemm_kernel<0><<<gg, 256>>>(K, Wv, bv, sv, lengths);

    attn_kernel<<<dim3(NN / 128, HH, BB), 128>>>(sq, sk, sv, lengths, so);

    ln_kernel<<<ROWS, 256>>>(so, g0, b0, st);

    gemm_kernel<1><<<gg, 256>>>(st, Wo, bo, su, nullptr);

    ln_kernel<<<ROWS, 256>>>(su, g1, b1, (float*)d_out);
}

// round 3
// speedup vs baseline: 1.3642x; 1.3642x over previous
#include <cuda_runtime.h>
#include <math.h>
#include <stdint.h>

#define BB 8
#define NN 1024
#define DD 256
#define HH 8
#define HD 32
#define ROWS (BB*NN)          // 8192
#define ELEMS (ROWS*DD)       // 2097152

// -------- scratch (static device globals; no allocation) --------
__device__ float g_q[ELEMS];
__device__ float g_k[ELEMS];
__device__ float g_v[ELEMS];
__device__ float g_o[ELEMS];
__device__ float g_t[ELEMS];
__device__ float g_u[ELEMS];

// ---------------- GEMM: C[8192,256] = X[8192,256] @ W[256,256] + bias ----------------
// MODE 0: projection, zero rows with n >= lengths[b]; skips fully-masked 64-row tiles
// MODE 1: C = X + relu(X@W + bias)   (residual MLP)
template<int MODE>
__global__ void __launch_bounds__(256) gemm_kernel(
    const float* __restrict__ X, const float* __restrict__ W,
    const float* __restrict__ bias, float* __restrict__ C,
    const int* __restrict__ lengths)
{
    __shared__ float As[16][68];   // [k][row], padded
    __shared__ float Bs[16][64];   // [k][col]

    const int tid  = threadIdx.x;
    const int brow = blockIdx.x * 64;
    const int bcol = blockIdx.y * 64;
    const int tx = tid & 15;
    const int ty = tid >> 4;

    if (MODE == 0) {
        const int blen = lengths[brow >> 10];
        if ((brow & 1023) >= blen) {
            // whole 64-row tile masked: write zeros, skip all compute
            float4 z = make_float4(0.f, 0.f, 0.f, 0.f);
            #pragma unroll
            for (int i = 0; i < 4; i++) {
                int idx = tid + i * 256;      // 0..1023 float4 slots (64x16)
                int r = idx >> 4, c4 = idx & 15;
                *(float4*)&C[(size_t)(brow + r) * DD + bcol + c4 * 4] = z;
            }
            return;
        }
    }

    float acc[4][4];
    #pragma unroll
    for (int i = 0; i < 4; i++)
        #pragma unroll
        for (int j = 0; j < 4; j++) acc[i][j] = 0.f;

    for (int k0 = 0; k0 < DD; k0 += 16) {
        {   // load A tile (64 rows x 16 k), one float4 per thread
            int r  = tid >> 2;
            int kc = (tid & 3) << 2;
            float4 xv = *(const float4*)&X[(size_t)(brow + r) * DD + k0 + kc];
            As[kc+0][r] = xv.x; As[kc+1][r] = xv.y;
            As[kc+2][r] = xv.z; As[kc+3][r] = xv.w;
        }
        {   // load B tile (16 k x 64 cols), one float4 per thread
            int r = tid >> 4;
            int c = (tid & 15) << 2;
            *(float4*)&Bs[r][c] = *(const float4*)&W[(size_t)(k0 + r) * DD + bcol + c];
        }
        __syncthreads();

        #pragma unroll
        for (int kk = 0; kk < 16; kk++) {
            float4 a4 = *(const float4*)&As[kk][ty << 2];
            float4 b4 = *(const float4*)&Bs[kk][tx << 2];
            float a[4] = {a4.x, a4.y, a4.z, a4.w};
            float b[4] = {b4.x, b4.y, b4.z, b4.w};
            #pragma unroll
            for (int i = 0; i < 4; i++)
                #pragma unroll
                for (int j = 0; j < 4; j++)
                    acc[i][j] += a[i] * b[j];
        }
        __syncthreads();
    }

    #pragma unroll
    for (int i = 0; i < 4; i++) {
        int gr = brow + (ty << 2) + i;
        int bidx = gr >> 10;
        int nidx = gr & 1023;
        #pragma unroll
        for (int j = 0; j < 4; j++) {
            int gc = bcol + (tx << 2) + j;
            float c = acc[i][j] + bias[gc];
            if (MODE == 0) {
                if (nidx >= lengths[bidx]) c = 0.f;
            } else {
                float t = X[(size_t)gr * DD + gc];
                c = t + fmaxf(c, 0.f);
            }
            C[(size_t)gr * DD + gc] = c;
        }
    }
}

// ---------------- Attention: per (b,h), O = qh + softmax_raw(q k^T/16) @ vh ----------------
// 512 threads = 4 groups x 128 q-rows; each group handles 1/4 of the keys (split-K in-block),
// partials combined through smem. grid (N/128, H, B).
#define AG 4
__global__ void __launch_bounds__(512) attn_kernel(
    const float* __restrict__ q, const float* __restrict__ k,
    const float* __restrict__ v, const int* __restrict__ lengths,
    float* __restrict__ o)
{
    extern __shared__ float sm[];   // [0,64KB): per-group tiles, reused as combine acc; +2KB esum
    const int b = blockIdx.z;
    const int h = blockIdx.y;
    const int len = lengths[b];
    const int tid = threadIdx.x;
    const int g = tid >> 7;          // group 0..3
    const int gtid = tid & 127;      // q-row within block
    const int n = blockIdx.x * 128 + gtid;

    float* orow = o + ((size_t)b * NN + n) * DD + h * HD;

    if (blockIdx.x * 128 >= len) {
        // entire q-range masked: zero output, no key streaming
        if (g == 0) {
            float4 z = make_float4(0.f, 0.f, 0.f, 0.f);
            #pragma unroll
            for (int j = 0; j < HD; j += 4) *(float4*)&orow[j] = z;
        }
        return;
    }

    float* ks = sm + g * 4096;       // 64 x 32 floats
    float* vs = ks + 2048;

    const float* qrow = q + ((size_t)b * NN + n) * DD + h * HD;
    float qr[HD];
    #pragma unroll
    for (int j = 0; j < HD; j += 4) {
        float4 t = *(const float4*)&qrow[j];
        qr[j] = t.x; qr[j+1] = t.y; qr[j+2] = t.z; qr[j+3] = t.w;
    }

    float acc[HD];
    #pragma unroll
    for (int j = 0; j < HD; j++) acc[j] = 0.f;
    float esum = 0.f;
    const bool active = (n < len);

    const int segLen = (len + AG - 1) >> 2;
    const int s0 = g * segLen;
    const int s1 = min(s0 + segLen, len);

    const float* kbase = k + (size_t)b * NN * DD + h * HD;
    const float* vbase = v + (size_t)b * NN * DD + h * HD;

    for (int m0 = s0; m0 < s1; m0 += 64) {
        asm volatile("bar.sync %0, 128;" :: "r"(g + 1) : "memory");
        #pragma unroll
        for (int i = 0; i < 4; i++) {
            int idx = gtid + i * 128;           // 0..511 float4 slots
            int r = idx >> 3;
            int c = (idx & 7) << 2;
            int row = m0 + r;
            if (row >= len) row = len - 1;      // clamp: stay in-bounds; rows >= mEnd unused
            size_t off = (size_t)row * DD + c;
            *(float4*)&ks[r * 32 + c] = *(const float4*)&kbase[off];
            *(float4*)&vs[r * 32 + c] = *(const float4*)&vbase[off];
        }
        asm volatile("bar.sync %0, 128;" :: "r"(g + 1) : "memory");

        const int mEnd = min(64, s1 - m0);
        if (active) {
            for (int mm = 0; mm < mEnd; mm++) {
                const float4* k4 = (const float4*)(ks + mm * 32);
                float p0 = 0.f, p1 = 0.f, p2 = 0.f, p3 = 0.f;   // 4 independent chains
                #pragma unroll
                for (int j4 = 0; j4 < 8; j4 += 4) {
                    float4 t0 = k4[j4+0], t1 = k4[j4+1], t2 = k4[j4+2], t3 = k4[j4+3];
                    p0 += qr[(j4+0)*4+0]*t0.x + qr[(j4+0)*4+1]*t0.y + qr[(j4+0)*4+2]*t0.z + qr[(j4+0)*4+3]*t0.w;
                    p1 += qr[(j4+1)*4+0]*t1.x + qr[(j4+1)*4+1]*t1.y + qr[(j4+1)*4+2]*t1.z + qr[(j4+1)*4+3]*t1.w;
                    p2 += qr[(j4+2)*4+0]*t2.x + qr[(j4+2)*4+1]*t2.y + qr[(j4+2)*4+2]*t2.z + qr[(j4+2)*4+3]*t2.w;
                    p3 += qr[(j4+3)*4+0]*t3.x + qr[(j4+3)*4+1]*t3.y + qr[(j4+3)*4+2]*t3.z + qr[(j4+3)*4+3]*t3.w;
                }
                float s = (p0 + p1) + (p2 + p3);
                float e = __expf(s * 0.0625f);   // scale 1/sqrt(DV) = 1/16
                esum += e;
                const float4* v4 = (const float4*)(vs + mm * 32);
                #pragma unroll
                for (int j4 = 0; j4 < 8; j4++) {
                    float4 t = v4[j4];
                    acc[j4*4+0] += e * t.x;
                    acc[j4*4+1] += e * t.y;
                    acc[j4*4+2] += e * t.z;
                    acc[j4*4+3] += e * t.w;
                }
            }
        }
    }

    // ---- combine partials across the 4 groups (reuse tile smem) ----
    __syncthreads();
    float* cacc = sm;                      // [AG*128][32]
    float* ces  = sm + AG * 128 * 32;      // [AG*128]
    {
        float* dst = cacc + (size_t)(g * 128 + gtid) * 32;
        #pragma unroll
        for (int j = 0; j < HD; j += 4)
            *(float4*)&dst[j] = make_float4(acc[j], acc[j+1], acc[j+2], acc[j+3]);
        ces[g * 128 + gtid] = active ? esum : 0.f;
    }
    __syncthreads();
    if (g == 0) {
        float tot = ces[gtid] + ces[128 + gtid] + ces[256 + gtid] + ces[384 + gtid];
        float inv = active ? (1.f / (tot + 1e-15f)) : 0.f;
        const float* a0 = cacc + (size_t)(0 * 128 + gtid) * 32;
        const float* a1 = cacc + (size_t)(1 * 128 + gtid) * 32;
        const float* a2 = cacc + (size_t)(2 * 128 + gtid) * 32;
        const float* a3 = cacc + (size_t)(3 * 128 + gtid) * 32;
        #pragma unroll
        for (int j = 0; j < HD; j += 4) {
            float4 x0 = *(const float4*)&a0[j];
            float4 x1 = *(const float4*)&a1[j];
            float4 x2 = *(const float4*)&a2[j];
            float4 x3 = *(const float4*)&a3[j];
            float4 t;
            t.x = active ? (qr[j+0] + (x0.x + x1.x + x2.x + x3.x) * inv) : 0.f;
            t.y = active ? (qr[j+1] + (x0.y + x1.y + x2.y + x3.y) * inv) : 0.f;
            t.z = active ? (qr[j+2] + (x0.z + x1.z + x2.z + x3.z) * inv) : 0.f;
            t.w = active ? (qr[j+3] + (x0.w + x1.w + x2.w + x3.w) * inv) : 0.f;
            *(float4*)&orow[j] = t;
        }
    }
}

// ---------------- LayerNorm over last dim (256), one block per row ----------------
__global__ void __launch_bounds__(256) ln_kernel(
    const float* __restrict__ x, const float* __restrict__ g,
    const float* __restrict__ b, float* __restrict__ y)
{
    const int row = blockIdx.x;
    const int t = threadIdx.x;
    __shared__ float sred[8];

    float v = x[(size_t)row * DD + t];

    float s = v;
    #pragma unroll
    for (int o = 16; o > 0; o >>= 1) s += __shfl_xor_sync(0xFFFFFFFFu, s, o);
    if ((t & 31) == 0) sred[t >> 5] = s;
    __syncthreads();
    float mu = 0.f;
    #pragma unroll
    for (int i = 0; i < 8; i++) mu += sred[i];
    mu *= (1.f / 256.f);

    float d = v - mu;
    float sq = d * d;
    #pragma unroll
    for (int o = 16; o > 0; o >>= 1) sq += __shfl_xor_sync(0xFFFFFFFFu, sq, o);
    __syncthreads();
    if ((t & 31) == 0) sred[t >> 5] = sq;
    __syncthreads();
    float var = 0.f;
    #pragma unroll
    for (int i = 0; i < 8; i++) var += sred[i];
    var *= (1.f / 256.f);

    float r = rsqrtf(var + 1e-5f);
    y[(size_t)row * DD + t] = d * r * g[t] + b[t];
}

// ---------------- launch ----------------
extern "C" void kernel_launch(void* const* d_in, const int* in_sizes, int n_in,
                              void* d_out, int out_size)
{
    const float* Q       = (const float*)d_in[0];
    const float* K       = (const float*)d_in[1];
    const int*   lengths = (const int*)  d_in[2];
    const float* Wq      = (const float*)d_in[3];
    const float* bq      = (const float*)d_in[4];
    const float* Wk      = (const float*)d_in[5];
    const float* bk      = (const float*)d_in[6];
    const float* Wv      = (const float*)d_in[7];
    const float* bv      = (const float*)d_in[8];
    const float* Wo      = (const float*)d_in[9];
    const float* bo      = (const float*)d_in[10];
    const float* g0      = (const float*)d_in[11];
    const float* b0      = (const float*)d_in[12];
    const float* g1      = (const float*)d_in[13];
    const float* b1      = (const float*)d_in[14];

    float *sq, *sk, *sv, *so, *st, *su;
    cudaGetSymbolAddress((void**)&sq, g_q);
    cudaGetSymbolAddress((void**)&sk, g_k);
    cudaGetSymbolAddress((void**)&sv, g_v);
    cudaGetSymbolAddress((void**)&so, g_o);
    cudaGetSymbolAddress((void**)&st, g_t);
    cudaGetSymbolAddress((void**)&su, g_u);

    dim3 gg(ROWS / 64, DD / 64);

    gemm_kernel<0><<<gg, 256>>>(Q, Wq, bq, sq, lengths);
    gemm_kernel<0><<<gg, 256>>>(K, Wk, bk, sk, lengths);
    gemm_kernel<0><<<gg, 256>>>(K, Wv, bv, sv, lengths);

    const int ATTN_SMEM = (AG * 4096 + AG * 128) * (int)sizeof(float);  // 64KB tiles + 2KB esum
    static int attn_cfg = 0;
    if (!attn_cfg) {
        cudaFuncSetAttribute(attn_kernel, cudaFuncAttributeMaxDynamicSharedMemorySize, ATTN_SMEM);
        attn_cfg = 1;
    }
    attn_kernel<<<dim3(NN / 128, HH, BB), 512, ATTN_SMEM>>>(sq, sk, sv, lengths, so);

    ln_kernel<<<ROWS, 256>>>(so, g0, b0, st);

    gemm_kernel<1><<<gg, 256>>>(st, Wo, bo, su, nullptr);

    ln_kernel<<<ROWS, 256>>>(su, g1, b1, (float*)d_out);
}

// round 4
// speedup vs baseline: 1.5780x; 1.1567x over previous
#include <cuda_runtime.h>
#include <math.h>
#include <stdint.h>

#define BB 8
#define NN 1024
#define DD 256
#define HH 8
#define HD 32
#define ROWS (BB*NN)          // 8192
#define ELEMS (ROWS*DD)       // 2097152

typedef unsigned long long u64;

// -------- scratch (static device globals; no allocation) --------
__device__ float g_q[ELEMS];
__device__ float g_k[ELEMS];
__device__ float g_v[ELEMS];
__device__ float g_o[ELEMS];
__device__ float g_t[ELEMS];
__device__ float g_u[ELEMS];

// ---------- packed f32x2 helpers (SASS FFMA2; PTX-only path) ----------
__device__ __forceinline__ u64 pk(float x, float y) {
    u64 r; asm("mov.b64 %0, {%1, %2};" : "=l"(r) : "f"(x), "f"(y)); return r;
}
__device__ __forceinline__ void upk(float& x, float& y, u64 p) {
    asm("mov.b64 {%0, %1}, %2;" : "=f"(x), "=f"(y) : "l"(p));
}
__device__ __forceinline__ u64 f2fma(u64 a, u64 b, u64 c) {
    u64 d; asm("fma.rn.f32x2 %0, %1, %2, %3;" : "=l"(d) : "l"(a), "l"(b), "l"(c)); return d;
}
__device__ __forceinline__ u64 f2add(u64 a, u64 b) {
    u64 d; asm("add.rn.f32x2 %0, %1, %2;" : "=l"(d) : "l"(a), "l"(b)); return d;
}
// 16B shared load directly into two packed f32x2 regs (no MOV packing)
__device__ __forceinline__ void lds2(u64& a, u64& b, uint32_t addr) {
    asm volatile("ld.shared.v2.b64 {%0, %1}, [%2];" : "=l"(a), "=l"(b) : "r"(addr));
}

// ---------------- GEMM: C[8192,256] = X[8192,256] @ W[256,256] + bias ----------------
// 64x128 tile, 256 threads, 4 rows x 8 cols per thread via FFMA2.
// MODE 0: projection, zero rows with n >= lengths[b]; skips fully-masked 64-row tiles
// MODE 1: C = X + relu(X@W + bias)
template<int MODE>
__global__ void __launch_bounds__(256) gemm_kernel(
    const float* __restrict__ X, const float* __restrict__ W,
    const float* __restrict__ bias, float* __restrict__ C,
    const int* __restrict__ lengths)
{
    __shared__ float As[16][68];    // [k][row], padded
    __shared__ float Bs[16][128];   // [k][col]

    const int tid  = threadIdx.x;
    const int brow = blockIdx.x * 64;
    const int bcol = blockIdx.y * 128;
    const int tx = tid & 15;        // col group (8 cols: tx*4 and 64+tx*4)
    const int ty = tid >> 4;        // row group (4 rows)

    if (MODE == 0) {
        const int blen = lengths[brow >> 10];
        if ((brow & 1023) >= blen) {
            float4 z = make_float4(0.f, 0.f, 0.f, 0.f);
            #pragma unroll
            for (int i = 0; i < 8; i++) {
                int idx = tid + i * 256;            // 0..2047 float4 slots (64x32)
                int r = idx >> 5, c4 = idx & 31;
                *(float4*)&C[(size_t)(brow + r) * DD + bcol + c4 * 4] = z;
            }
            return;
        }
    }

    u64 acc[4][4];
    #pragma unroll
    for (int i = 0; i < 4; i++)
        #pragma unroll
        for (int p = 0; p < 4; p++) acc[i][p] = 0ull;

    const uint32_t bs_base = (uint32_t)__cvta_generic_to_shared(&Bs[0][0]);

    for (int k0 = 0; k0 < DD; k0 += 16) {
        {   // A tile: 64 rows x 16 k
            int r  = tid >> 2;
            int kc = (tid & 3) << 2;
            float4 xv = *(const float4*)&X[(size_t)(brow + r) * DD + k0 + kc];
            As[kc+0][r] = xv.x; As[kc+1][r] = xv.y;
            As[kc+2][r] = xv.z; As[kc+3][r] = xv.w;
        }
        {   // B tile: 16 k x 128 cols (2 float4 per thread)
            #pragma unroll
            for (int i = 0; i < 2; i++) {
                int idx = tid + i * 256;            // 0..511
                int r = idx >> 5, c = (idx & 31) << 2;
                *(float4*)&Bs[r][c] = *(const float4*)&W[(size_t)(k0 + r) * DD + bcol + c];
            }
        }
        __syncthreads();

        #pragma unroll
        for (int kk = 0; kk < 16; kk++) {
            float4 a4 = *(const float4*)&As[kk][ty << 2];
            u64 bp0, bp1, bp2, bp3;
            uint32_t baddr = bs_base + (uint32_t)(kk * 128 + (tx << 2)) * 4u;
            lds2(bp0, bp1, baddr);          // cols tx*4 .. +3
            lds2(bp2, bp3, baddr + 256u);   // cols 64+tx*4 .. +3
            u64 aa;
            aa = pk(a4.x, a4.x);
            acc[0][0]=f2fma(aa,bp0,acc[0][0]); acc[0][1]=f2fma(aa,bp1,acc[0][1]);
            acc[0][2]=f2fma(aa,bp2,acc[0][2]); acc[0][3]=f2fma(aa,bp3,acc[0][3]);
            aa = pk(a4.y, a4.y);
            acc[1][0]=f2fma(aa,bp0,acc[1][0]); acc[1][1]=f2fma(aa,bp1,acc[1][1]);
            acc[1][2]=f2fma(aa,bp2,acc[1][2]); acc[1][3]=f2fma(aa,bp3,acc[1][3]);
            aa = pk(a4.z, a4.z);
            acc[2][0]=f2fma(aa,bp0,acc[2][0]); acc[2][1]=f2fma(aa,bp1,acc[2][1]);
            acc[2][2]=f2fma(aa,bp2,acc[2][2]); acc[2][3]=f2fma(aa,bp3,acc[2][3]);
            aa = pk(a4.w, a4.w);
            acc[3][0]=f2fma(aa,bp0,acc[3][0]); acc[3][1]=f2fma(aa,bp1,acc[3][1]);
            acc[3][2]=f2fma(aa,bp2,acc[3][2]); acc[3][3]=f2fma(aa,bp3,acc[3][3]);
        }
        __syncthreads();
    }

    const int c0 = bcol + (tx << 2);
    const int c1 = bcol + 64 + (tx << 2);
    float4 bv0 = *(const float4*)&bias[c0];
    float4 bv1 = *(const float4*)&bias[c1];

    #pragma unroll
    for (int i = 0; i < 4; i++) {
        int gr = brow + (ty << 2) + i;
        int bidx = gr >> 10;
        int nidx = gr & 1023;
        float4 o0, o1;
        upk(o0.x, o0.y, acc[i][0]); upk(o0.z, o0.w, acc[i][1]);
        upk(o1.x, o1.y, acc[i][2]); upk(o1.z, o1.w, acc[i][3]);
        o0.x += bv0.x; o0.y += bv0.y; o0.z += bv0.z; o0.w += bv0.w;
        o1.x += bv1.x; o1.y += bv1.y; o1.z += bv1.z; o1.w += bv1.w;
        if (MODE == 0) {
            if (nidx >= lengths[bidx]) {
                o0 = make_float4(0.f,0.f,0.f,0.f);
                o1 = make_float4(0.f,0.f,0.f,0.f);
            }
        } else {
            float4 r0 = *(const float4*)&X[(size_t)gr * DD + c0];
            float4 r1 = *(const float4*)&X[(size_t)gr * DD + c1];
            o0.x = r0.x + fmaxf(o0.x, 0.f); o0.y = r0.y + fmaxf(o0.y, 0.f);
            o0.z = r0.z + fmaxf(o0.z, 0.f); o0.w = r0.w + fmaxf(o0.w, 0.f);
            o1.x = r1.x + fmaxf(o1.x, 0.f); o1.y = r1.y + fmaxf(o1.y, 0.f);
            o1.z = r1.z + fmaxf(o1.z, 0.f); o1.w = r1.w + fmaxf(o1.w, 0.f);
        }
        *(float4*)&C[(size_t)gr * DD + c0] = o0;
        *(float4*)&C[(size_t)gr * DD + c1] = o1;
    }
}

// ---------------- Attention: per (b,h), O = qh + softmax_raw(q k^T/16) @ vh ----------------
// 512 threads = 4 groups x 128 q-rows; group handles 1/4 of keys; FFMA2 inner loops.
#define AG 4
__global__ void __launch_bounds__(512) attn_kernel(
    const float* __restrict__ q, const float* __restrict__ k,
    const float* __restrict__ v, const int* __restrict__ lengths,
    float* __restrict__ o)
{
    extern __shared__ float sm[];   // 4 x (64x32 k + 64x32 v) tiles; reused for combine
    const int b = blockIdx.z;
    const int h = blockIdx.y;
    const int len = lengths[b];
    const int tid = threadIdx.x;
    const int g = tid >> 7;
    const int gtid = tid & 127;
    const int n = blockIdx.x * 128 + gtid;

    float* orow = o + ((size_t)b * NN + n) * DD + h * HD;

    if (blockIdx.x * 128 >= len) {
        if (g == 0) {
            float4 z = make_float4(0.f, 0.f, 0.f, 0.f);
            #pragma unroll
            for (int j = 0; j < HD; j += 4) *(float4*)&orow[j] = z;
        }
        return;
    }

    float* ks = sm + g * 4096;
    float* vs = ks + 2048;
    const uint32_t ks_base = (uint32_t)__cvta_generic_to_shared(ks);
    const uint32_t vs_base = (uint32_t)__cvta_generic_to_shared(vs);

    const float* qrow = q + ((size_t)b * NN + n) * DD + h * HD;
    u64 qp[16];
    #pragma unroll
    for (int j = 0; j < HD; j += 4) {
        float4 t = *(const float4*)&qrow[j];
        qp[j/2]     = pk(t.x, t.y);
        qp[j/2 + 1] = pk(t.z, t.w);
    }

    u64 acc2[16];
    #pragma unroll
    for (int j = 0; j < 16; j++) acc2[j] = 0ull;
    float esum = 0.f;
    const bool active = (n < len);

    const int segLen = (len + AG - 1) >> 2;
    const int s0 = g * segLen;
    const int s1 = min(s0 + segLen, len);

    const float* kbase = k + (size_t)b * NN * DD + h * HD;
    const float* vbase = v + (size_t)b * NN * DD + h * HD;

    for (int m0 = s0; m0 < s1; m0 += 64) {
        asm volatile("bar.sync %0, 128;" :: "r"(g + 1) : "memory");
        #pragma unroll
        for (int i = 0; i < 4; i++) {
            int idx = gtid + i * 128;
            int r = idx >> 3;
            int c = (idx & 7) << 2;
            int row = m0 + r;
            if (row >= len) row = len - 1;
            size_t off = (size_t)row * DD + c;
            *(float4*)&ks[r * 32 + c] = *(const float4*)&kbase[off];
            *(float4*)&vs[r * 32 + c] = *(const float4*)&vbase[off];
        }
        asm volatile("bar.sync %0, 128;" :: "r"(g + 1) : "memory");

        const int mEnd = min(64, s1 - m0);
        if (active) {
            uint32_t ka = ks_base, va = vs_base;
            for (int mm = 0; mm < mEnd; mm++) {
                u64 kp[16];
                #pragma unroll
                for (int j = 0; j < 8; j++) lds2(kp[2*j], kp[2*j+1], ka + j * 16u);
                u64 c0 = 0ull, c1 = 0ull, c2 = 0ull, c3 = 0ull;
                #pragma unroll
                for (int j = 0; j < 4; j++) {
                    c0 = f2fma(qp[4*j+0], kp[4*j+0], c0);
                    c1 = f2fma(qp[4*j+1], kp[4*j+1], c1);
                    c2 = f2fma(qp[4*j+2], kp[4*j+2], c2);
                    c3 = f2fma(qp[4*j+3], kp[4*j+3], c3);
                }
                u64 sp = f2add(f2add(c0, c1), f2add(c2, c3));
                float sx, sy; upk(sx, sy, sp);
                float e = __expf((sx + sy) * 0.0625f);   // scale 1/sqrt(DV) = 1/16
                esum += e;
                u64 ep = pk(e, e);
                u64 vp[16];
                #pragma unroll
                for (int j = 0; j < 8; j++) lds2(vp[2*j], vp[2*j+1], va + j * 16u);
                #pragma unroll
                for (int j = 0; j < 16; j++) acc2[j] = f2fma(ep, vp[j], acc2[j]);
                ka += 128u; va += 128u;
            }
        }
    }

    // ---- combine partials across groups (reuse tile smem) ----
    __syncthreads();
    float* cacc = sm;                      // [AG*128][32]
    float* ces  = sm + AG * 128 * 32;      // [AG*128]
    {
        float* dst = cacc + (size_t)(g * 128 + gtid) * 32;
        #pragma unroll
        for (int j = 0; j < 16; j += 2) {
            float4 t;
            upk(t.x, t.y, acc2[j]); upk(t.z, t.w, acc2[j+1]);
            *(float4*)&dst[j * 2] = t;
        }
        ces[g * 128 + gtid] = active ? esum : 0.f;
    }
    __syncthreads();
    if (g == 0) {
        float tot = ces[gtid] + ces[128 + gtid] + ces[256 + gtid] + ces[384 + gtid];
        float inv = active ? (1.f / (tot + 1e-15f)) : 0.f;
        const float* a0 = cacc + (size_t)(0 * 128 + gtid) * 32;
        const float* a1 = cacc + (size_t)(1 * 128 + gtid) * 32;
        const float* a2 = cacc + (size_t)(2 * 128 + gtid) * 32;
        const float* a3 = cacc + (size_t)(3 * 128 + gtid) * 32;
        #pragma unroll
        for (int j = 0; j < HD; j += 4) {
            float4 x0 = *(const float4*)&a0[j];
            float4 x1 = *(const float4*)&a1[j];
            float4 x2 = *(const float4*)&a2[j];
            float4 x3 = *(const float4*)&a3[j];
            float qx, qy, qz, qw;
            upk(qx, qy, qp[j/2]); upk(qz, qw, qp[j/2 + 1]);
            float4 t;
            t.x = active ? (qx + (x0.x + x1.x + x2.x + x3.x) * inv) : 0.f;
            t.y = active ? (qy + (x0.y + x1.y + x2.y + x3.y) * inv) : 0.f;
            t.z = active ? (qz + (x0.z + x1.z + x2.z + x3.z) * inv) : 0.f;
            t.w = active ? (qw + (x0.w + x1.w + x2.w + x3.w) * inv) : 0.f;
            *(float4*)&orow[j] = t;
        }
    }
}

// ---------------- LayerNorm over last dim (256), one block per row ----------------
__global__ void __launch_bounds__(256) ln_kernel(
    const float* __restrict__ x, const float* __restrict__ g,
    const float* __restrict__ b, float* __restrict__ y)
{
    const int row = blockIdx.x;
    const int t = threadIdx.x;
    __shared__ float sred[8];

    float v = x[(size_t)row * DD + t];

    float s = v;
    #pragma unroll
    for (int o = 16; o > 0; o >>= 1) s += __shfl_xor_sync(0xFFFFFFFFu, s, o);
    if ((t & 31) == 0) sred[t >> 5] = s;
    __syncthreads();
    float mu = 0.f;
    #pragma unroll
    for (int i = 0; i < 8; i++) mu += sred[i];
    mu *= (1.f / 256.f);

    float d = v - mu;
    float sq = d * d;
    #pragma unroll
    for (int o = 16; o > 0; o >>= 1) sq += __shfl_xor_sync(0xFFFFFFFFu, sq, o);
    __syncthreads();
    if ((t & 31) == 0) sred[t >> 5] = sq;
    __syncthreads();
    float var = 0.f;
    #pragma unroll
    for (int i = 0; i < 8; i++) var += sred[i];
    var *= (1.f / 256.f);

    float r = rsqrtf(var + 1e-5f);
    y[(size_t)row * DD + t] = d * r * g[t] + b[t];
}

// ---------------- launch ----------------
extern "C" void kernel_launch(void* const* d_in, const int* in_sizes, int n_in,
                              void* d_out, int out_size)
{
    const float* Q       = (const float*)d_in[0];
    const float* K       = (const float*)d_in[1];
    const int*   lengths = (const int*)  d_in[2];
    const float* Wq      = (const float*)d_in[3];
    const float* bq      = (const float*)d_in[4];
    const float* Wk      = (const float*)d_in[5];
    const float* bk      = (const float*)d_in[6];
    const float* Wv      = (const float*)d_in[7];
    const float* bv      = (const float*)d_in[8];
    const float* Wo      = (const float*)d_in[9];
    const float* bo      = (const float*)d_in[10];
    const float* g0      = (const float*)d_in[11];
    const float* b0      = (const float*)d_in[12];
    const float* g1      = (const float*)d_in[13];
    const float* b1      = (const float*)d_in[14];

    float *sq, *sk, *sv, *so, *st, *su;
    cudaGetSymbolAddress((void**)&sq, g_q);
    cudaGetSymbolAddress((void**)&sk, g_k);
    cudaGetSymbolAddress((void**)&sv, g_v);
    cudaGetSymbolAddress((void**)&so, g_o);
    cudaGetSymbolAddress((void**)&st, g_t);
    cudaGetSymbolAddress((void**)&su, g_u);

    dim3 gg(ROWS / 64, DD / 128);

    gemm_kernel<0><<<gg, 256>>>(Q, Wq, bq, sq, lengths);
    gemm_kernel<0><<<gg, 256>>>(K, Wk, bk, sk, lengths);
    gemm_kernel<0><<<gg, 256>>>(K, Wv, bv, sv, lengths);

    const int ATTN_SMEM = (AG * 4096 + AG * 128) * (int)sizeof(float);
    static int attn_cfg = 0;
    if (!attn_cfg) {
        cudaFuncSetAttribute(attn_kernel, cudaFuncAttributeMaxDynamicSharedMemorySize, ATTN_SMEM);
        attn_cfg = 1;
    }
    attn_kernel<<<dim3(NN / 128, HH, BB), 512, ATTN_SMEM>>>(sq, sk, sv, lengths, so);

    ln_kernel<<<ROWS, 256>>>(so, g0, b0, st);

    gemm_kernel<1><<<gg, 256>>>(st, Wo, bo, su, nullptr);

    ln_kernel<<<ROWS, 256>>>(su, g1, b1, (float*)d_out);
}